// round 12
// baseline (speedup 1.0000x reference)
#include <cuda_runtime.h>
#include <cstdint>

// Problem constants
#define B_   4
#define S_   2048
#define D_   1024
#define H_   16
#define HD_  64
#define BH_  (B_ * H_)          // 64
#define NKT_ 16                 // key tiles (of 128) per row -> partial-sum slots

// Scratch (allocation-free rule: __device__ globals)
__device__ float g_Q[B_ * S_ * D_];
__device__ float g_K[B_ * S_ * D_];
__device__ float g_V[B_ * S_ * D_];
__device__ float g_X[B_ * S_ * D_];
__device__ float g_rsp[(size_t)BH_ * S_ * NKT_];   // per-(row, ktile) partial exp sums

// ---------------------------------------------------------------------------
// C[m,n] = sum_k A[m,k] * W[n,k] + bias[n]     (M=8192, N=1024, K=1024)
// 128x128 tile, BK=8, 8x8 per thread, 256 threads.
// ---------------------------------------------------------------------------
__global__ __launch_bounds__(256)
void gemm_abt_kernel(const float* __restrict__ A, const float* __restrict__ W,
                     const float* __restrict__ bias, float* __restrict__ C)
{
    constexpr int N = 1024, K = 1024;
    __shared__ float As[8][128];
    __shared__ float Bs[8][128];

    const int tid = threadIdx.x;
    const int m0  = blockIdx.y * 128;
    const int n0  = blockIdx.x * 128;
    const int lr  = tid >> 1;            // 0..127
    const int lc  = (tid & 1) << 2;      // 0 or 4
    const int tx  = tid & 15;            // n sub-tile
    const int ty  = tid >> 4;            // m sub-tile

    const float* Ap = A + (size_t)(m0 + lr) * K + lc;
    const float* Wp = W + (size_t)(n0 + lr) * K + lc;

    float acc[8][8] = {};

    for (int kt = 0; kt < K; kt += 8) {
        float4 a4 = *reinterpret_cast<const float4*>(Ap + kt);
        float4 b4 = *reinterpret_cast<const float4*>(Wp + kt);
        As[lc + 0][lr] = a4.x; As[lc + 1][lr] = a4.y;
        As[lc + 2][lr] = a4.z; As[lc + 3][lr] = a4.w;
        Bs[lc + 0][lr] = b4.x; Bs[lc + 1][lr] = b4.y;
        Bs[lc + 2][lr] = b4.z; Bs[lc + 3][lr] = b4.w;
        __syncthreads();

        #pragma unroll
        for (int k = 0; k < 8; k++) {
            float ra[8], rb[8];
            #pragma unroll
            for (int i = 0; i < 8; i++) ra[i] = As[k][ty * 8 + i];
            #pragma unroll
            for (int j = 0; j < 8; j++) rb[j] = Bs[k][tx * 8 + j];
            #pragma unroll
            for (int i = 0; i < 8; i++) {
                #pragma unroll
                for (int j = 0; j < 8; j++) {
                    acc[i][j] = fmaf(ra[i], rb[j], acc[i][j]);
                }
            }
        }
        __syncthreads();
    }

    float bb[8];
    #pragma unroll
    for (int j = 0; j < 8; j++) bb[j] = bias[n0 + tx * 8 + j];

    #pragma unroll
    for (int i = 0; i < 8; i++) {
        float* Cp = C + (size_t)(m0 + ty * 8 + i) * N + n0 + tx * 8;
        float4 v0 = make_float4(acc[i][0] + bb[0], acc[i][1] + bb[1],
                                acc[i][2] + bb[2], acc[i][3] + bb[3]);
        float4 v1 = make_float4(acc[i][4] + bb[4], acc[i][5] + bb[5],
                                acc[i][6] + bb[6], acc[i][7] + bb[7]);
        *reinterpret_cast<float4*>(Cp)     = v0;
        *reinterpret_cast<float4*>(Cp + 4) = v1;
    }
}

// ---------------------------------------------------------------------------
// Scores: P[bh, q, k] = exp(mask ? q·k / 8 : -inf)  (unnormalized),
// plus per-(row, ktile) partial exp sums (deterministic, no atomics).
// One block = one (bh, 128q x 128k) tile. grid = (16, 16, 64).
// No max-subtraction: logits are bounded (|l| <~ 20), exp(-1e10) -> 0 matches mask.
// ---------------------------------------------------------------------------
__global__ __launch_bounds__(256)
void scores_kernel(const float* __restrict__ Q, const float* __restrict__ Kmat,
                   const int* __restrict__ mask, float* __restrict__ P,
                   float* __restrict__ rsp)
{
    __shared__ float As[8][128];
    __shared__ float Bs[8][128];
    __shared__ float red[128][17];   // padded to avoid bank conflicts

    const int tid = threadIdx.x;
    const int bh  = blockIdx.z;
    const int b   = bh >> 4;
    const int h   = bh & 15;
    const int q0  = blockIdx.y * 128;
    const int k0  = blockIdx.x * 128;
    const int lr  = tid >> 1;
    const int lc  = (tid & 1) << 2;
    const int tx  = tid & 15;
    const int ty  = tid >> 4;

    const float* Qp = Q    + (size_t)(b * S_ + q0 + lr) * D_ + h * HD_ + lc;
    const float* Kp = Kmat + (size_t)(b * S_ + k0 + lr) * D_ + h * HD_ + lc;

    float acc[8][8] = {};

    #pragma unroll
    for (int kt = 0; kt < HD_; kt += 8) {
        float4 a4 = *reinterpret_cast<const float4*>(Qp + kt);
        float4 b4 = *reinterpret_cast<const float4*>(Kp + kt);
        As[lc + 0][lr] = a4.x; As[lc + 1][lr] = a4.y;
        As[lc + 2][lr] = a4.z; As[lc + 3][lr] = a4.w;
        Bs[lc + 0][lr] = b4.x; Bs[lc + 1][lr] = b4.y;
        Bs[lc + 2][lr] = b4.z; Bs[lc + 3][lr] = b4.w;
        __syncthreads();

        #pragma unroll
        for (int k = 0; k < 8; k++) {
            float ra[8], rb[8];
            #pragma unroll
            for (int i = 0; i < 8; i++) ra[i] = As[k][ty * 8 + i];
            #pragma unroll
            for (int j = 0; j < 8; j++) rb[j] = Bs[k][tx * 8 + j];
            #pragma unroll
            for (int i = 0; i < 8; i++) {
                #pragma unroll
                for (int j = 0; j < 8; j++) {
                    acc[i][j] = fmaf(ra[i], rb[j], acc[i][j]);
                }
            }
        }
        __syncthreads();
    }

    // mask + exp + partial row sums
    int km[8];
    #pragma unroll
    for (int j = 0; j < 8; j++) km[j] = mask[b * S_ + k0 + tx * 8 + j];

    #pragma unroll
    for (int i = 0; i < 8; i++) {
        float s = 0.f;
        #pragma unroll
        for (int j = 0; j < 8; j++) {
            float v = km[j] ? __expf(acc[i][j] * 0.125f) : 0.f;
            acc[i][j] = v;
            s += v;
        }
        red[ty * 8 + i][tx] = s;
    }

    // store unnormalized P (normalized in-place by av_kernel)
    float* Pb = P + (size_t)bh * S_ * S_;
    #pragma unroll
    for (int i = 0; i < 8; i++) {
        float* pp = Pb + (size_t)(q0 + ty * 8 + i) * S_ + k0 + tx * 8;
        float4 v0 = make_float4(acc[i][0], acc[i][1], acc[i][2], acc[i][3]);
        float4 v1 = make_float4(acc[i][4], acc[i][5], acc[i][6], acc[i][7]);
        *reinterpret_cast<float4*>(pp)     = v0;
        *reinterpret_cast<float4*>(pp + 4) = v1;
    }

    __syncthreads();
    if (tid < 128) {
        float s = 0.f;
        #pragma unroll
        for (int t = 0; t < 16; t++) s += red[tid][t];
        rsp[((size_t)bh * S_ + q0 + tid) * NKT_ + blockIdx.x] = s;
    }
}

// ---------------------------------------------------------------------------
// AV: X = (P / rowsum) @ V, per (bh, 256q-row tile). Also rewrites P in-place
// as the normalized attention (each element read/written exactly once).
// grid = (8, 64). 256q x 64hd tile, BK=16, 8x8 per thread.
// ---------------------------------------------------------------------------
__global__ __launch_bounds__(256)
void av_kernel(float* __restrict__ P, const float* __restrict__ V,
               const float* __restrict__ rsp, float* __restrict__ X)
{
    __shared__ float As[16][256];
    __shared__ float Bs[16][64];
    __shared__ float invs[256];

    const int tid = threadIdx.x;
    const int bh  = blockIdx.y;
    const int b   = bh >> 4;
    const int h   = bh & 15;
    const int q0  = blockIdx.x * 256;

    {
        const float* rp = rsp + ((size_t)bh * S_ + q0 + tid) * NKT_;
        float s = 0.f;
        #pragma unroll
        for (int t = 0; t < 16; t++) s += rp[t];
        invs[tid] = 1.0f / s;
    }
    __syncthreads();

    const int tx   = tid & 7;          // 8 col groups * 8 = 64 cols
    const int ty   = tid >> 3;         // 32 row groups * 8 = 256 rows
    const int pcol = (tid & 3) << 2;   // 0,4,8,12
    const int prow = tid >> 2;         // 0..63
    const int vrow = tid >> 4;         // 0..15
    const int vcol = (tid & 15) << 2;  // 0..60

    float acc[8][8] = {};
    float* Pb       = P + (size_t)bh * S_ * S_;
    const float* Vb = V + (size_t)b * S_ * D_ + h * HD_;

    for (int kt = 0; kt < S_; kt += 16) {
        #pragma unroll
        for (int rr = 0; rr < 4; rr++) {
            const int row = prow + rr * 64;
            const float inv = invs[row];
            float* pp = Pb + (size_t)(q0 + row) * S_ + kt + pcol;
            float4 p4 = *reinterpret_cast<const float4*>(pp);
            p4.x *= inv; p4.y *= inv; p4.z *= inv; p4.w *= inv;
            As[pcol + 0][row] = p4.x; As[pcol + 1][row] = p4.y;
            As[pcol + 2][row] = p4.z; As[pcol + 3][row] = p4.w;
            *reinterpret_cast<float4*>(pp) = p4;   // normalized attention out
        }
        {
            const float4 v4 = *reinterpret_cast<const float4*>(
                Vb + (size_t)(kt + vrow) * D_ + vcol);
            *reinterpret_cast<float4*>(&Bs[vrow][vcol]) = v4;
        }
        __syncthreads();

        #pragma unroll
        for (int k = 0; k < 16; k++) {
            float ra[8], rb[8];
            #pragma unroll
            for (int i = 0; i < 8; i++) ra[i] = As[k][ty * 8 + i];
            #pragma unroll
            for (int j = 0; j < 8; j++) rb[j] = Bs[k][tx * 8 + j];
            #pragma unroll
            for (int i = 0; i < 8; i++) {
                #pragma unroll
                for (int j = 0; j < 8; j++) {
                    acc[i][j] = fmaf(ra[i], rb[j], acc[i][j]);
                }
            }
        }
        __syncthreads();
    }

    // X in [B, S, D] layout so the output projection consumes it directly
    #pragma unroll
    for (int i = 0; i < 8; i++) {
        float* xp = X + (size_t)(b * S_ + q0 + ty * 8 + i) * D_ + h * HD_ + tx * 8;
        float4 v0 = make_float4(acc[i][0], acc[i][1], acc[i][2], acc[i][3]);
        float4 v1 = make_float4(acc[i][4], acc[i][5], acc[i][6], acc[i][7]);
        *reinterpret_cast<float4*>(xp)     = v0;
        *reinterpret_cast<float4*>(xp + 4) = v1;
    }
}

// ---------------------------------------------------------------------------
extern "C" void kernel_launch(void* const* d_in, const int* in_sizes, int n_in,
                              void* d_out, int out_size)
{
    (void)in_sizes; (void)n_in; (void)out_size;

    const float* query = (const float*)d_in[0];
    const float* key_  = (const float*)d_in[1];
    const float* value = (const float*)d_in[2];
    const int*   mask  = (const int*)d_in[3];
    const float* Wq    = (const float*)d_in[4];
    const float* bq    = (const float*)d_in[5];
    const float* Wk    = (const float*)d_in[6];
    const float* bk    = (const float*)d_in[7];
    const float* Wv    = (const float*)d_in[8];
    const float* bv    = (const float*)d_in[9];
    const float* Wo    = (const float*)d_in[10];
    const float* bo    = (const float*)d_in[11];

    float* xout = (float*)d_out;                              // [B,S,D]
    float* pout = xout + (size_t)B_ * S_ * D_;                // [B,H,S,S]

    void *pQ, *pK, *pV, *pX, *pR;
    cudaGetSymbolAddress(&pQ, g_Q);
    cudaGetSymbolAddress(&pK, g_K);
    cudaGetSymbolAddress(&pV, g_V);
    cudaGetSymbolAddress(&pX, g_X);
    cudaGetSymbolAddress(&pR, g_rsp);

    const dim3 gproj(1024 / 128, 8192 / 128);   // (8, 64)

    gemm_abt_kernel<<<gproj, 256>>>(query, Wq, bq, (float*)pQ);
    gemm_abt_kernel<<<gproj, 256>>>(key_,  Wk, bk, (float*)pK);
    gemm_abt_kernel<<<gproj, 256>>>(value, Wv, bv, (float*)pV);

    scores_kernel<<<dim3(S_ / 128, S_ / 128, BH_), 256>>>(
        (const float*)pQ, (const float*)pK, mask, pout, (float*)pR);

    av_kernel<<<dim3(S_ / 256, BH_), 256>>>(
        pout, (const float*)pV, (const float*)pR, (float*)pX);

    gemm_abt_kernel<<<gproj, 256>>>((const float*)pX, Wo, bo, xout);
}

// round 15
// speedup vs baseline: 1.4642x; 1.4642x over previous
#include <cuda_runtime.h>
#include <cuda_fp16.h>
#include <cstdint>

// Problem constants
#define B_   4
#define S_   2048
#define D_   1024
#define H_   16
#define HD_  64
#define BH_  (B_ * H_)          // 64
#define NKT_ 16                 // key tiles (of 128) per row -> partial-sum slots

// Scratch (allocation-free rule: __device__ globals)
__device__ float g_Q[B_ * S_ * D_];
__device__ float g_K[B_ * S_ * D_];
__device__ float g_V[B_ * S_ * D_];
__device__ float g_X[B_ * S_ * D_];
__device__ float g_rsp[(size_t)BH_ * S_ * NKT_];

// ============================================================================
// PTX helpers — baseline ISA only (ldmatrix sm_75+, mma.sync sm_80+).
// NO tcgen05/wgmma: build targets plain sm_103 (no 'a'), arch-specific
// features are rejected by ptxas.
// ============================================================================
__device__ __forceinline__ uint32_t smem_u32(const void* p) {
    uint32_t a;
    asm("{ .reg .u64 t; cvta.to.shared.u64 t, %1; cvt.u32.u64 %0, t; }"
        : "=r"(a) : "l"(p));
    return a;
}

__device__ __forceinline__ void ldmat_x4(uint32_t* r, uint32_t addr) {
    asm volatile("ldmatrix.sync.aligned.m8n8.x4.shared.b16 {%0,%1,%2,%3}, [%4];"
        : "=r"(r[0]), "=r"(r[1]), "=r"(r[2]), "=r"(r[3]) : "r"(addr));
}
__device__ __forceinline__ void ldmat_x2(uint32_t* r, uint32_t addr) {
    asm volatile("ldmatrix.sync.aligned.m8n8.x2.shared.b16 {%0,%1}, [%2];"
        : "=r"(r[0]), "=r"(r[1]) : "r"(addr));
}
// D += A * B, m16n8k16, fp16 in, fp32 accumulate
__device__ __forceinline__ void mma16816(float* d, const uint32_t* a,
                                         const uint32_t* b) {
    asm volatile("mma.sync.aligned.m16n8k16.row.col.f32.f16.f16.f32 "
        "{%0,%1,%2,%3}, {%4,%5,%6,%7}, {%8,%9}, {%0,%1,%2,%3};"
        : "+f"(d[0]), "+f"(d[1]), "+f"(d[2]), "+f"(d[3])
        : "r"(a[0]), "r"(a[1]), "r"(a[2]), "r"(a[3]), "r"(b[0]), "r"(b[1]));
}

__device__ __forceinline__ uint32_t pack2(__half a, __half b) {
    __half2 h = __halves2half2(a, b);
    return *reinterpret_cast<uint32_t*>(&h);
}

// ============================================================================
// Projection GEMM on tensor pipe (mma.sync, fp16x3 split precision):
// C[m,n] = sum_k A[m,k] * W[n,k] + bias[n]    (M=8192, N=1024, K=1024)
// CTA tile 128m x 128n, k-chunk 32, double-buffered SMEM, 256 threads.
// Each warp: 64m x 32n = 4 x 4 fragments of m16n8k16.
// SMEM rows padded to 40 halves (80B) -> conflict-free ldmatrix.
// ============================================================================
#define AH_OFF 0
#define AL_OFF 10240
#define WH_OFF 20480
#define WL_OFF 30720
#define PBUF   40960
#define PROJ_SMEM (2 * PBUF)     // 81920 bytes

__global__ __launch_bounds__(256, 1)
void proj_mma_kernel(const float* __restrict__ A, const float* __restrict__ W,
                     const float* __restrict__ bias, float* __restrict__ C)
{
    extern __shared__ __align__(16) char smem[];
    const uint32_t sb = smem_u32(smem);

    const int tid  = threadIdx.x;
    const int wid  = tid >> 5;
    const int lane = tid & 31;
    const int m0   = blockIdx.y * 128;
    const int n0   = blockIdx.x * 128;
    const int wm   = wid >> 2;           // 0..1 -> 64-row slab
    const int wn   = wid & 3;            // 0..3 -> 32-col slab

    const float* Ab = A + (size_t)m0 * D_;
    const float* Wb = W + (size_t)n0 * D_;

    // per-thread fill coordinates (tile 128 rows x 8 float4)
    int frow[4], fc4[4];
    #pragma unroll
    for (int i = 0; i < 4; i++) {
        int idx = tid + i * 256;
        frow[i] = idx >> 3;
        fc4[i]  = idx & 7;
    }

    // ldmatrix lane base addresses (bytes)
    const uint32_t aBase = sb +
        (uint32_t)(((wm * 64 + (lane & 15)) * 40 + (lane >> 4) * 8) * 2);
    const uint32_t bBase = sb +
        (uint32_t)(((wn * 32 + (lane & 7)) * 40 + ((lane >> 3) & 1) * 8) * 2);

    float acc[4][4][4] = {};

    float4 va[4], vw[4];
    #pragma unroll
    for (int i = 0; i < 4; i++) {
        va[i] = __ldg((const float4*)(Ab + (size_t)frow[i] * D_ + fc4[i] * 4));
        vw[i] = __ldg((const float4*)(Wb + (size_t)frow[i] * D_ + fc4[i] * 4));
    }

    for (int it = 0; it < 32; it++) {
        const int buf = it & 1;
        char* bp = smem + buf * PBUF;

        // split fp32 -> (hi, lo) fp16 and store to SMEM
        #pragma unroll
        for (int i = 0; i < 4; i++) {
            const uint32_t off = (uint32_t)(frow[i] * 80 + fc4[i] * 8);
            float x0 = va[i].x, x1 = va[i].y, x2 = va[i].z, x3 = va[i].w;
            __half h0 = __float2half_rn(x0), h1 = __float2half_rn(x1);
            __half h2 = __float2half_rn(x2), h3 = __float2half_rn(x3);
            __half l0 = __float2half_rn(x0 - __half2float(h0));
            __half l1 = __float2half_rn(x1 - __half2float(h1));
            __half l2 = __float2half_rn(x2 - __half2float(h2));
            __half l3 = __float2half_rn(x3 - __half2float(h3));
            *reinterpret_cast<uint2*>(bp + AH_OFF + off) =
                make_uint2(pack2(h0, h1), pack2(h2, h3));
            *reinterpret_cast<uint2*>(bp + AL_OFF + off) =
                make_uint2(pack2(l0, l1), pack2(l2, l3));

            x0 = vw[i].x; x1 = vw[i].y; x2 = vw[i].z; x3 = vw[i].w;
            h0 = __float2half_rn(x0); h1 = __float2half_rn(x1);
            h2 = __float2half_rn(x2); h3 = __float2half_rn(x3);
            l0 = __float2half_rn(x0 - __half2float(h0));
            l1 = __float2half_rn(x1 - __half2float(h1));
            l2 = __float2half_rn(x2 - __half2float(h2));
            l3 = __float2half_rn(x3 - __half2float(h3));
            *reinterpret_cast<uint2*>(bp + WH_OFF + off) =
                make_uint2(pack2(h0, h1), pack2(h2, h3));
            *reinterpret_cast<uint2*>(bp + WL_OFF + off) =
                make_uint2(pack2(l0, l1), pack2(l2, l3));
        }
        __syncthreads();

        // prefetch next k-chunk while computing this one
        if (it < 31) {
            const int kt = (it + 1) * 32;
            #pragma unroll
            for (int i = 0; i < 4; i++) {
                va[i] = __ldg((const float4*)(Ab + (size_t)frow[i] * D_ + kt + fc4[i] * 4));
                vw[i] = __ldg((const float4*)(Wb + (size_t)frow[i] * D_ + kt + fc4[i] * 4));
            }
        }

        const uint32_t bo = (uint32_t)(buf * PBUF);
        #pragma unroll
        for (int ks = 0; ks < 2; ks++) {
            uint32_t ah[4][4], al[4][4], wh[4][2], wl[4][2];
            #pragma unroll
            for (int mf = 0; mf < 4; mf++) {
                ldmat_x4(ah[mf], aBase + bo + AH_OFF + mf * 1280 + ks * 32);
                ldmat_x4(al[mf], aBase + bo + AL_OFF + mf * 1280 + ks * 32);
            }
            #pragma unroll
            for (int nf = 0; nf < 4; nf++) {
                ldmat_x2(wh[nf], bBase + bo + WH_OFF + nf * 640 + ks * 32);
                ldmat_x2(wl[nf], bBase + bo + WL_OFF + nf * 640 + ks * 32);
            }
            #pragma unroll
            for (int mf = 0; mf < 4; mf++) {
                #pragma unroll
                for (int nf = 0; nf < 4; nf++) {
                    mma16816(acc[mf][nf], ah[mf], wh[nf]);
                    mma16816(acc[mf][nf], ah[mf], wl[nf]);
                    mma16816(acc[mf][nf], al[mf], wh[nf]);
                }
            }
        }
        __syncthreads();
    }

    // Epilogue: fragment layout m16n8 -> rows (lane/4, lane/4+8), cols (lane%4)*2
    const int r0 = m0 + wm * 64 + (lane >> 2);
    #pragma unroll
    for (int mf = 0; mf < 4; mf++) {
        #pragma unroll
        for (int nf = 0; nf < 4; nf++) {
            const int c = n0 + wn * 32 + nf * 8 + (lane & 3) * 2;
            const float2 bv = *reinterpret_cast<const float2*>(bias + c);
            float* p0 = C + (size_t)(r0 + mf * 16) * D_ + c;
            float* p1 = C + (size_t)(r0 + mf * 16 + 8) * D_ + c;
            *reinterpret_cast<float2*>(p0) =
                make_float2(acc[mf][nf][0] + bv.x, acc[mf][nf][1] + bv.y);
            *reinterpret_cast<float2*>(p1) =
                make_float2(acc[mf][nf][2] + bv.x, acc[mf][nf][3] + bv.y);
        }
    }
}

// ---------------------------------------------------------------------------
// Scores: P[bh, q, k] = exp(mask ? q·k / 8 : -inf)  (unnormalized) + partial
// row sums. One block = one (bh, 128q x 128k) tile. (SIMT fp32, known good)
// ---------------------------------------------------------------------------
__global__ __launch_bounds__(256)
void scores_kernel(const float* __restrict__ Q, const float* __restrict__ Kmat,
                   const int* __restrict__ mask, float* __restrict__ P,
                   float* __restrict__ rsp)
{
    __shared__ float As[8][128];
    __shared__ float Bs[8][128];
    __shared__ float red[128][17];

    const int tid = threadIdx.x;
    const int bh  = blockIdx.z;
    const int b   = bh >> 4;
    const int h   = bh & 15;
    const int q0  = blockIdx.y * 128;
    const int k0  = blockIdx.x * 128;
    const int lr  = tid >> 1;
    const int lc  = (tid & 1) << 2;
    const int tx  = tid & 15;
    const int ty  = tid >> 4;

    const float* Qp = Q    + (size_t)(b * S_ + q0 + lr) * D_ + h * HD_ + lc;
    const float* Kp = Kmat + (size_t)(b * S_ + k0 + lr) * D_ + h * HD_ + lc;

    float acc[8][8] = {};

    #pragma unroll
    for (int kt = 0; kt < HD_; kt += 8) {
        float4 a4 = *reinterpret_cast<const float4*>(Qp + kt);
        float4 b4 = *reinterpret_cast<const float4*>(Kp + kt);
        As[lc + 0][lr] = a4.x; As[lc + 1][lr] = a4.y;
        As[lc + 2][lr] = a4.z; As[lc + 3][lr] = a4.w;
        Bs[lc + 0][lr] = b4.x; Bs[lc + 1][lr] = b4.y;
        Bs[lc + 2][lr] = b4.z; Bs[lc + 3][lr] = b4.w;
        __syncthreads();

        #pragma unroll
        for (int k = 0; k < 8; k++) {
            float ra[8], rb[8];
            #pragma unroll
            for (int i = 0; i < 8; i++) ra[i] = As[k][ty * 8 + i];
            #pragma unroll
            for (int j = 0; j < 8; j++) rb[j] = Bs[k][tx * 8 + j];
            #pragma unroll
            for (int i = 0; i < 8; i++)
                #pragma unroll
                for (int j = 0; j < 8; j++)
                    acc[i][j] = fmaf(ra[i], rb[j], acc[i][j]);
        }
        __syncthreads();
    }

    int km[8];
    #pragma unroll
    for (int j = 0; j < 8; j++) km[j] = mask[b * S_ + k0 + tx * 8 + j];

    #pragma unroll
    for (int i = 0; i < 8; i++) {
        float s = 0.f;
        #pragma unroll
        for (int j = 0; j < 8; j++) {
            float v = km[j] ? __expf(acc[i][j] * 0.125f) : 0.f;
            acc[i][j] = v;
            s += v;
        }
        red[ty * 8 + i][tx] = s;
    }

    float* Pb = P + (size_t)bh * S_ * S_;
    #pragma unroll
    for (int i = 0; i < 8; i++) {
        float* pp = Pb + (size_t)(q0 + ty * 8 + i) * S_ + k0 + tx * 8;
        *reinterpret_cast<float4*>(pp) =
            make_float4(acc[i][0], acc[i][1], acc[i][2], acc[i][3]);
        *reinterpret_cast<float4*>(pp + 4) =
            make_float4(acc[i][4], acc[i][5], acc[i][6], acc[i][7]);
    }

    __syncthreads();
    if (tid < 128) {
        float s = 0.f;
        #pragma unroll
        for (int t = 0; t < 16; t++) s += red[tid][t];
        rsp[((size_t)bh * S_ + q0 + tid) * NKT_ + blockIdx.x] = s;
    }
}

// ---------------------------------------------------------------------------
// AV: X = (P / rowsum) @ V; rewrites P in-place as normalized attention.
// (SIMT fp32, known good)
// ---------------------------------------------------------------------------
__global__ __launch_bounds__(256)
void av_kernel(float* __restrict__ P, const float* __restrict__ V,
               const float* __restrict__ rsp, float* __restrict__ X)
{
    __shared__ float As[16][256];
    __shared__ float Bs[16][64];
    __shared__ float invs[256];

    const int tid = threadIdx.x;
    const int bh  = blockIdx.y;
    const int b   = bh >> 4;
    const int h   = bh & 15;
    const int q0  = blockIdx.x * 256;

    {
        const float* rp = rsp + ((size_t)bh * S_ + q0 + tid) * NKT_;
        float s = 0.f;
        #pragma unroll
        for (int t = 0; t < 16; t++) s += rp[t];
        invs[tid] = 1.0f / s;
    }
    __syncthreads();

    const int tx   = tid & 7;
    const int ty   = tid >> 3;
    const int pcol = (tid & 3) << 2;
    const int prow = tid >> 2;
    const int vrow = tid >> 4;
    const int vcol = (tid & 15) << 2;

    float acc[8][8] = {};
    float* Pb       = P + (size_t)bh * S_ * S_;
    const float* Vb = V + (size_t)b * S_ * D_ + h * HD_;

    for (int kt = 0; kt < S_; kt += 16) {
        #pragma unroll
        for (int rr = 0; rr < 4; rr++) {
            const int row = prow + rr * 64;
            const float inv = invs[row];
            float* pp = Pb + (size_t)(q0 + row) * S_ + kt + pcol;
            float4 p4 = *reinterpret_cast<const float4*>(pp);
            p4.x *= inv; p4.y *= inv; p4.z *= inv; p4.w *= inv;
            As[pcol + 0][row] = p4.x; As[pcol + 1][row] = p4.y;
            As[pcol + 2][row] = p4.z; As[pcol + 3][row] = p4.w;
            *reinterpret_cast<float4*>(pp) = p4;
        }
        {
            const float4 v4 = *reinterpret_cast<const float4*>(
                Vb + (size_t)(kt + vrow) * D_ + vcol);
            *reinterpret_cast<float4*>(&Bs[vrow][vcol]) = v4;
        }
        __syncthreads();

        #pragma unroll
        for (int k = 0; k < 16; k++) {
            float ra[8], rb[8];
            #pragma unroll
            for (int i = 0; i < 8; i++) ra[i] = As[k][ty * 8 + i];
            #pragma unroll
            for (int j = 0; j < 8; j++) rb[j] = Bs[k][tx * 8 + j];
            #pragma unroll
            for (int i = 0; i < 8; i++)
                #pragma unroll
                for (int j = 0; j < 8; j++)
                    acc[i][j] = fmaf(ra[i], rb[j], acc[i][j]);
        }
        __syncthreads();
    }

    #pragma unroll
    for (int i = 0; i < 8; i++) {
        float* xp = X + (size_t)(b * S_ + q0 + ty * 8 + i) * D_ + h * HD_ + tx * 8;
        *reinterpret_cast<float4*>(xp) =
            make_float4(acc[i][0], acc[i][1], acc[i][2], acc[i][3]);
        *reinterpret_cast<float4*>(xp + 4) =
            make_float4(acc[i][4], acc[i][5], acc[i][6], acc[i][7]);
    }
}

// ---------------------------------------------------------------------------
extern "C" void kernel_launch(void* const* d_in, const int* in_sizes, int n_in,
                              void* d_out, int out_size)
{
    (void)in_sizes; (void)n_in; (void)out_size;

    const float* query = (const float*)d_in[0];
    const float* key_  = (const float*)d_in[1];
    const float* value = (const float*)d_in[2];
    const int*   mask  = (const int*)d_in[3];
    const float* Wq    = (const float*)d_in[4];
    const float* bq    = (const float*)d_in[5];
    const float* Wk    = (const float*)d_in[6];
    const float* bk    = (const float*)d_in[7];
    const float* Wv    = (const float*)d_in[8];
    const float* bv    = (const float*)d_in[9];
    const float* Wo    = (const float*)d_in[10];
    const float* bo    = (const float*)d_in[11];

    float* xout = (float*)d_out;                 // [B,S,D]
    float* pout = xout + (size_t)B_ * S_ * D_;   // [B,H,S,S]

    void *pQ, *pK, *pV, *pX, *pR;
    cudaGetSymbolAddress(&pQ, g_Q);
    cudaGetSymbolAddress(&pK, g_K);
    cudaGetSymbolAddress(&pV, g_V);
    cudaGetSymbolAddress(&pX, g_X);
    cudaGetSymbolAddress(&pR, g_rsp);

    cudaFuncSetAttribute(proj_mma_kernel,
                         cudaFuncAttributeMaxDynamicSharedMemorySize, PROJ_SMEM);

    const dim3 gproj(D_ / 128, (B_ * S_) / 128);   // (8, 64)

    proj_mma_kernel<<<gproj, 256, PROJ_SMEM>>>(query, Wq, bq, (float*)pQ);
    proj_mma_kernel<<<gproj, 256, PROJ_SMEM>>>(key_,  Wk, bk, (float*)pK);
    proj_mma_kernel<<<gproj, 256, PROJ_SMEM>>>(value, Wv, bv, (float*)pV);

    scores_kernel<<<dim3(S_ / 128, S_ / 128, BH_), 256>>>(
        (const float*)pQ, (const float*)pK, mask, pout, (float*)pR);

    av_kernel<<<dim3(S_ / 256, BH_), 256>>>(
        pout, (const float*)pV, (const float*)pR, (float*)pX);

    proj_mma_kernel<<<gproj, 256, PROJ_SMEM>>>((const float*)pX, Wo, bo, xout);
}

// round 16
// speedup vs baseline: 1.8820x; 1.2854x over previous
#include <cuda_runtime.h>
#include <cuda_fp16.h>
#include <cstdint>

// Problem constants
#define B_   4
#define S_   2048
#define D_   1024
#define H_   16
#define HD_  64
#define BH_  (B_ * H_)          // 64
#define NKT_ 16                 // key tiles (of 128) per row -> partial-sum slots

// Scratch (allocation-free rule: __device__ globals)
__device__ float g_Q[B_ * S_ * D_];
__device__ float g_K[B_ * S_ * D_];
__device__ float g_V[B_ * S_ * D_];
__device__ float g_X[B_ * S_ * D_];
__device__ float g_rsp[(size_t)BH_ * S_ * NKT_];

// ============================================================================
// PTX helpers — baseline ISA only (ldmatrix sm_75+, mma.sync sm_80+).
// ============================================================================
__device__ __forceinline__ uint32_t smem_u32(const void* p) {
    uint32_t a;
    asm("{ .reg .u64 t; cvta.to.shared.u64 t, %1; cvt.u32.u64 %0, t; }"
        : "=r"(a) : "l"(p));
    return a;
}

__device__ __forceinline__ void ldmat_x4(uint32_t* r, uint32_t addr) {
    asm volatile("ldmatrix.sync.aligned.m8n8.x4.shared.b16 {%0,%1,%2,%3}, [%4];"
        : "=r"(r[0]), "=r"(r[1]), "=r"(r[2]), "=r"(r[3]) : "r"(addr));
}
__device__ __forceinline__ void ldmat_x2(uint32_t* r, uint32_t addr) {
    asm volatile("ldmatrix.sync.aligned.m8n8.x2.shared.b16 {%0,%1}, [%2];"
        : "=r"(r[0]), "=r"(r[1]) : "r"(addr));
}
__device__ __forceinline__ void ldmat_x2_trans(uint32_t* r, uint32_t addr) {
    asm volatile("ldmatrix.sync.aligned.m8n8.x2.trans.shared.b16 {%0,%1}, [%2];"
        : "=r"(r[0]), "=r"(r[1]) : "r"(addr));
}
// D += A * B, m16n8k16, fp16 in, fp32 accumulate
__device__ __forceinline__ void mma16816(float* d, const uint32_t* a,
                                         const uint32_t* b) {
    asm volatile("mma.sync.aligned.m16n8k16.row.col.f32.f16.f16.f32 "
        "{%0,%1,%2,%3}, {%4,%5,%6,%7}, {%8,%9}, {%0,%1,%2,%3};"
        : "+f"(d[0]), "+f"(d[1]), "+f"(d[2]), "+f"(d[3])
        : "r"(a[0]), "r"(a[1]), "r"(a[2]), "r"(a[3]), "r"(b[0]), "r"(b[1]));
}

__device__ __forceinline__ uint32_t pack2(__half a, __half b) {
    __half2 h = __halves2half2(a, b);
    return *reinterpret_cast<uint32_t*>(&h);
}

// split one float4 into hi/lo fp16x2 pairs
__device__ __forceinline__ void split4(float4 v, uint2& hi, uint2& lo) {
    __half h0 = __float2half_rn(v.x), h1 = __float2half_rn(v.y);
    __half h2 = __float2half_rn(v.z), h3 = __float2half_rn(v.w);
    __half l0 = __float2half_rn(v.x - __half2float(h0));
    __half l1 = __float2half_rn(v.y - __half2float(h1));
    __half l2 = __float2half_rn(v.z - __half2float(h2));
    __half l3 = __float2half_rn(v.w - __half2float(h3));
    hi = make_uint2(pack2(h0, h1), pack2(h2, h3));
    lo = make_uint2(pack2(l0, l1), pack2(l2, l3));
}

// ============================================================================
// Projection GEMM (unchanged from R14 — proven): mma.sync fp16x3
// C[m,n] = sum_k A[m,k] * W[n,k] + bias[n]    (M=8192, N=1024, K=1024)
// ============================================================================
#define AH_OFF 0
#define AL_OFF 10240
#define WH_OFF 20480
#define WL_OFF 30720
#define PBUF   40960
#define PROJ_SMEM (2 * PBUF)     // 81920 bytes

__global__ __launch_bounds__(256, 1)
void proj_mma_kernel(const float* __restrict__ A, const float* __restrict__ W,
                     const float* __restrict__ bias, float* __restrict__ C)
{
    extern __shared__ __align__(16) char smem[];
    const uint32_t sb = smem_u32(smem);

    const int tid  = threadIdx.x;
    const int wid  = tid >> 5;
    const int lane = tid & 31;
    const int m0   = blockIdx.y * 128;
    const int n0   = blockIdx.x * 128;
    const int wm   = wid >> 2;
    const int wn   = wid & 3;

    const float* Ab = A + (size_t)m0 * D_;
    const float* Wb = W + (size_t)n0 * D_;

    int frow[4], fc4[4];
    #pragma unroll
    for (int i = 0; i < 4; i++) {
        int idx = tid + i * 256;
        frow[i] = idx >> 3;
        fc4[i]  = idx & 7;
    }

    const uint32_t aBase = sb +
        (uint32_t)(((wm * 64 + (lane & 15)) * 40 + (lane >> 4) * 8) * 2);
    const uint32_t bBase = sb +
        (uint32_t)(((wn * 32 + (lane & 7)) * 40 + ((lane >> 3) & 1) * 8) * 2);

    float acc[4][4][4] = {};

    float4 va[4], vw[4];
    #pragma unroll
    for (int i = 0; i < 4; i++) {
        va[i] = __ldg((const float4*)(Ab + (size_t)frow[i] * D_ + fc4[i] * 4));
        vw[i] = __ldg((const float4*)(Wb + (size_t)frow[i] * D_ + fc4[i] * 4));
    }

    for (int it = 0; it < 32; it++) {
        const int buf = it & 1;
        char* bp = smem + buf * PBUF;

        #pragma unroll
        for (int i = 0; i < 4; i++) {
            const uint32_t off = (uint32_t)(frow[i] * 80 + fc4[i] * 8);
            uint2 hi, lo;
            split4(va[i], hi, lo);
            *reinterpret_cast<uint2*>(bp + AH_OFF + off) = hi;
            *reinterpret_cast<uint2*>(bp + AL_OFF + off) = lo;
            split4(vw[i], hi, lo);
            *reinterpret_cast<uint2*>(bp + WH_OFF + off) = hi;
            *reinterpret_cast<uint2*>(bp + WL_OFF + off) = lo;
        }
        __syncthreads();

        if (it < 31) {
            const int kt = (it + 1) * 32;
            #pragma unroll
            for (int i = 0; i < 4; i++) {
                va[i] = __ldg((const float4*)(Ab + (size_t)frow[i] * D_ + kt + fc4[i] * 4));
                vw[i] = __ldg((const float4*)(Wb + (size_t)frow[i] * D_ + kt + fc4[i] * 4));
            }
        }

        const uint32_t bo = (uint32_t)(buf * PBUF);
        #pragma unroll
        for (int ks = 0; ks < 2; ks++) {
            uint32_t ah[4][4], al[4][4], wh[4][2], wl[4][2];
            #pragma unroll
            for (int mf = 0; mf < 4; mf++) {
                ldmat_x4(ah[mf], aBase + bo + AH_OFF + mf * 1280 + ks * 32);
                ldmat_x4(al[mf], aBase + bo + AL_OFF + mf * 1280 + ks * 32);
            }
            #pragma unroll
            for (int nf = 0; nf < 4; nf++) {
                ldmat_x2(wh[nf], bBase + bo + WH_OFF + nf * 640 + ks * 32);
                ldmat_x2(wl[nf], bBase + bo + WL_OFF + nf * 640 + ks * 32);
            }
            #pragma unroll
            for (int mf = 0; mf < 4; mf++) {
                #pragma unroll
                for (int nf = 0; nf < 4; nf++) {
                    mma16816(acc[mf][nf], ah[mf], wh[nf]);
                    mma16816(acc[mf][nf], ah[mf], wl[nf]);
                    mma16816(acc[mf][nf], al[mf], wh[nf]);
                }
            }
        }
        __syncthreads();
    }

    const int r0 = m0 + wm * 64 + (lane >> 2);
    #pragma unroll
    for (int mf = 0; mf < 4; mf++) {
        #pragma unroll
        for (int nf = 0; nf < 4; nf++) {
            const int c = n0 + wn * 32 + nf * 8 + (lane & 3) * 2;
            const float2 bv = *reinterpret_cast<const float2*>(bias + c);
            float* p0 = C + (size_t)(r0 + mf * 16) * D_ + c;
            float* p1 = C + (size_t)(r0 + mf * 16 + 8) * D_ + c;
            *reinterpret_cast<float2*>(p0) =
                make_float2(acc[mf][nf][0] + bv.x, acc[mf][nf][1] + bv.y);
            *reinterpret_cast<float2*>(p1) =
                make_float2(acc[mf][nf][2] + bv.x, acc[mf][nf][3] + bv.y);
        }
    }
}

// ============================================================================
// Scores on tensor pipe: P[bh,q,k] = mask ? exp(q·k/8) : 0 (unnormalized) +
// per-(row, 128k-tile) partial sums. CTA = 128q x 128k, fp16x3 split QK^T.
// SMEM rows padded to 72 halves (144B) -> conflict-free ldmatrix.
// ============================================================================
#define SQH 0
#define SQL 18432
#define SKH 36864
#define SKL 55296
#define SCORES_SMEM 73728

__global__ __launch_bounds__(256, 1)
void scores_mma_kernel(const float* __restrict__ Q, const float* __restrict__ Kmat,
                       const int* __restrict__ mask, float* __restrict__ P,
                       float* __restrict__ rsp)
{
    extern __shared__ __align__(16) char smem[];
    __shared__ float red[128][5];
    const uint32_t sb = smem_u32(smem);

    const int tid  = threadIdx.x;
    const int wid  = tid >> 5;
    const int lane = tid & 31;
    const int bh   = blockIdx.z;
    const int b    = bh >> 4;
    const int h    = bh & 15;
    const int q0   = blockIdx.y * 128;
    const int k0   = blockIdx.x * 128;
    const int wm   = wid >> 2;
    const int wn   = wid & 3;

    // load + split Q/K tiles (128 rows x 64 cols each)
    const float* Qp = Q    + (size_t)(b * S_ + q0) * D_ + h * HD_;
    const float* Kp = Kmat + (size_t)(b * S_ + k0) * D_ + h * HD_;
    #pragma unroll
    for (int i = 0; i < 8; i++) {
        int idx = tid + i * 256;
        int r = idx >> 4, c4 = idx & 15;
        const uint32_t off = (uint32_t)(r * 144 + c4 * 8);
        uint2 hi, lo;
        split4(__ldg((const float4*)(Qp + (size_t)r * D_ + c4 * 4)), hi, lo);
        *reinterpret_cast<uint2*>(smem + SQH + off) = hi;
        *reinterpret_cast<uint2*>(smem + SQL + off) = lo;
        split4(__ldg((const float4*)(Kp + (size_t)r * D_ + c4 * 4)), hi, lo);
        *reinterpret_cast<uint2*>(smem + SKH + off) = hi;
        *reinterpret_cast<uint2*>(smem + SKL + off) = lo;
    }
    __syncthreads();

    const uint32_t arow = (uint32_t)((wm * 64 + (lane & 15)) * 144 + (lane >> 4) * 16);
    const uint32_t brow = (uint32_t)((wn * 32 + (lane & 7)) * 144 + ((lane >> 3) & 1) * 16);

    float acc[4][4][4] = {};
    #pragma unroll
    for (int ks = 0; ks < 4; ks++) {
        uint32_t qh[4][4], ql[4][4], kh[4][2], kl[4][2];
        #pragma unroll
        for (int mf = 0; mf < 4; mf++) {
            ldmat_x4(qh[mf], sb + SQH + arow + mf * 2304 + ks * 32);
            ldmat_x4(ql[mf], sb + SQL + arow + mf * 2304 + ks * 32);
        }
        #pragma unroll
        for (int nf = 0; nf < 4; nf++) {
            ldmat_x2(kh[nf], sb + SKH + brow + nf * 1152 + ks * 32);
            ldmat_x2(kl[nf], sb + SKL + brow + nf * 1152 + ks * 32);
        }
        #pragma unroll
        for (int mf = 0; mf < 4; mf++) {
            #pragma unroll
            for (int nf = 0; nf < 4; nf++) {
                mma16816(acc[mf][nf], qh[mf], kh[nf]);
                mma16816(acc[mf][nf], qh[mf], kl[nf]);
                mma16816(acc[mf][nf], ql[mf], kh[nf]);
            }
        }
    }

    // epilogue: mask + exp + row sums + store P
    const int rl = lane >> 2;
    const int cl = (lane & 3) * 2;
    float* Pb = P + (size_t)bh * S_ * S_;

    #pragma unroll
    for (int mf = 0; mf < 4; mf++) {
        float s_lo = 0.f, s_hi = 0.f;
        const int r = q0 + wm * 64 + mf * 16 + rl;
        #pragma unroll
        for (int nf = 0; nf < 4; nf++) {
            const int c = k0 + wn * 32 + nf * 8 + cl;
            const int2 m2 = *reinterpret_cast<const int2*>(&mask[b * S_ + c]);
            float e0 = m2.x ? __expf(acc[mf][nf][0] * 0.125f) : 0.f;
            float e1 = m2.y ? __expf(acc[mf][nf][1] * 0.125f) : 0.f;
            float e2 = m2.x ? __expf(acc[mf][nf][2] * 0.125f) : 0.f;
            float e3 = m2.y ? __expf(acc[mf][nf][3] * 0.125f) : 0.f;
            s_lo += e0 + e1;
            s_hi += e2 + e3;
            *reinterpret_cast<float2*>(&Pb[(size_t)r * S_ + c]) = make_float2(e0, e1);
            *reinterpret_cast<float2*>(&Pb[(size_t)(r + 8) * S_ + c]) = make_float2(e2, e3);
        }
        s_lo += __shfl_xor_sync(0xffffffffu, s_lo, 1);
        s_lo += __shfl_xor_sync(0xffffffffu, s_lo, 2);
        s_hi += __shfl_xor_sync(0xffffffffu, s_hi, 1);
        s_hi += __shfl_xor_sync(0xffffffffu, s_hi, 2);
        if ((lane & 3) == 0) {
            red[wm * 64 + mf * 16 + rl][wn]     = s_lo;
            red[wm * 64 + mf * 16 + rl + 8][wn] = s_hi;
        }
    }
    __syncthreads();
    if (tid < 128) {
        float s = red[tid][0] + red[tid][1] + red[tid][2] + red[tid][3];
        rsp[((size_t)bh * S_ + q0 + tid) * NKT_ + blockIdx.x] = s;
    }
}

// ============================================================================
// AV on tensor pipe: X = (P/rowsum) @ V; rewrites P in-place normalized (fp32).
// CTA = 128q x 64hd, k chunks of 64, fp16x3 split. V B-frag via ldmatrix.trans.
// ============================================================================
#define APH 0
#define APL 18432
#define AVH 36864
#define AVL 46080
#define AV_SMEM 55296

__global__ __launch_bounds__(256, 1)
void av_mma_kernel(float* __restrict__ P, const float* __restrict__ V,
                   const float* __restrict__ rsp, float* __restrict__ X)
{
    extern __shared__ __align__(16) char smem[];
    __shared__ float invs[128];
    const uint32_t sb = smem_u32(smem);

    const int tid  = threadIdx.x;
    const int wid  = tid >> 5;
    const int lane = tid & 31;
    const int bh   = blockIdx.y;
    const int b    = bh >> 4;
    const int h    = bh & 15;
    const int q0   = blockIdx.x * 128;
    const int wm   = wid >> 1;          // 0..3 -> 32-row slab
    const int wn   = wid & 1;           // 0..1 -> 32-col slab

    if (tid < 128) {
        const float* rp = rsp + ((size_t)bh * S_ + q0 + tid) * NKT_;
        float s = 0.f;
        #pragma unroll
        for (int t = 0; t < 16; t++) s += rp[t];
        invs[tid] = 1.0f / s;
    }
    __syncthreads();

    float acc[2][4][4] = {};
    float* Pb       = P + (size_t)bh * S_ * S_;
    const float* Vb = V + (size_t)b * S_ * D_ + h * HD_;

    const uint32_t arow = (uint32_t)((wm * 32 + (lane & 15)) * 144 + (lane >> 4) * 16);
    const uint32_t bofs = (uint32_t)(((lane & 15)) * 144 + (wn * 32) * 2);

    for (int kt = 0; kt < 32; kt++) {
        const int k0 = kt * 64;

        // P chunk: normalize (fp32), write back, split to fp16 hi/lo
        #pragma unroll
        for (int i = 0; i < 8; i++) {
            int idx = tid + i * 256;
            int r = idx >> 4, c4 = idx & 15;
            float* pp = Pb + (size_t)(q0 + r) * S_ + k0 + c4 * 4;
            float4 p = *reinterpret_cast<const float4*>(pp);
            const float inv = invs[r];
            p.x *= inv; p.y *= inv; p.z *= inv; p.w *= inv;
            *reinterpret_cast<float4*>(pp) = p;
            uint2 hi, lo;
            split4(p, hi, lo);
            const uint32_t off = (uint32_t)(r * 144 + c4 * 8);
            *reinterpret_cast<uint2*>(smem + APH + off) = hi;
            *reinterpret_cast<uint2*>(smem + APL + off) = lo;
        }
        // V chunk: 64 x 64, split
        #pragma unroll
        for (int i = 0; i < 4; i++) {
            int idx = tid + i * 256;
            int r = idx >> 4, c4 = idx & 15;
            uint2 hi, lo;
            split4(__ldg((const float4*)(Vb + (size_t)(k0 + r) * D_ + c4 * 4)), hi, lo);
            const uint32_t off = (uint32_t)(r * 144 + c4 * 8);
            *reinterpret_cast<uint2*>(smem + AVH + off) = hi;
            *reinterpret_cast<uint2*>(smem + AVL + off) = lo;
        }
        __syncthreads();

        #pragma unroll
        for (int ks = 0; ks < 4; ks++) {
            uint32_t ph[2][4], pl[2][4], vh[4][2], vl[4][2];
            #pragma unroll
            for (int mf = 0; mf < 2; mf++) {
                ldmat_x4(ph[mf], sb + APH + arow + mf * 2304 + ks * 32);
                ldmat_x4(pl[mf], sb + APL + arow + mf * 2304 + ks * 32);
            }
            #pragma unroll
            for (int nf = 0; nf < 4; nf++) {
                const uint32_t ba = sb + bofs + ks * 16 * 144 + nf * 16;
                ldmat_x2_trans(vh[nf], AVH + ba);
                ldmat_x2_trans(vl[nf], AVL + ba);
            }
            #pragma unroll
            for (int mf = 0; mf < 2; mf++) {
                #pragma unroll
                for (int nf = 0; nf < 4; nf++) {
                    mma16816(acc[mf][nf], ph[mf], vh[nf]);
                    mma16816(acc[mf][nf], ph[mf], vl[nf]);
                    mma16816(acc[mf][nf], pl[mf], vh[nf]);
                }
            }
        }
        __syncthreads();
    }

    // epilogue: X in [B,S,D]
    #pragma unroll
    for (int mf = 0; mf < 2; mf++) {
        const int r = q0 + wm * 32 + mf * 16 + (lane >> 2);
        #pragma unroll
        for (int nf = 0; nf < 4; nf++) {
            const int c = h * HD_ + wn * 32 + nf * 8 + (lane & 3) * 2;
            float* p0 = X + (size_t)(b * S_ + r) * D_ + c;
            float* p1 = X + (size_t)(b * S_ + r + 8) * D_ + c;
            *reinterpret_cast<float2*>(p0) = make_float2(acc[mf][nf][0], acc[mf][nf][1]);
            *reinterpret_cast<float2*>(p1) = make_float2(acc[mf][nf][2], acc[mf][nf][3]);
        }
    }
}

// ---------------------------------------------------------------------------
extern "C" void kernel_launch(void* const* d_in, const int* in_sizes, int n_in,
                              void* d_out, int out_size)
{
    (void)in_sizes; (void)n_in; (void)out_size;

    const float* query = (const float*)d_in[0];
    const float* key_  = (const float*)d_in[1];
    const float* value = (const float*)d_in[2];
    const int*   mask  = (const int*)d_in[3];
    const float* Wq    = (const float*)d_in[4];
    const float* bq    = (const float*)d_in[5];
    const float* Wk    = (const float*)d_in[6];
    const float* bk    = (const float*)d_in[7];
    const float* Wv    = (const float*)d_in[8];
    const float* bv    = (const float*)d_in[9];
    const float* Wo    = (const float*)d_in[10];
    const float* bo    = (const float*)d_in[11];

    float* xout = (float*)d_out;                 // [B,S,D]
    float* pout = xout + (size_t)B_ * S_ * D_;   // [B,H,S,S]

    void *pQ, *pK, *pV, *pX, *pR;
    cudaGetSymbolAddress(&pQ, g_Q);
    cudaGetSymbolAddress(&pK, g_K);
    cudaGetSymbolAddress(&pV, g_V);
    cudaGetSymbolAddress(&pX, g_X);
    cudaGetSymbolAddress(&pR, g_rsp);

    cudaFuncSetAttribute(proj_mma_kernel,
                         cudaFuncAttributeMaxDynamicSharedMemorySize, PROJ_SMEM);
    cudaFuncSetAttribute(scores_mma_kernel,
                         cudaFuncAttributeMaxDynamicSharedMemorySize, SCORES_SMEM);
    cudaFuncSetAttribute(av_mma_kernel,
                         cudaFuncAttributeMaxDynamicSharedMemorySize, AV_SMEM);

    const dim3 gproj(D_ / 128, (B_ * S_) / 128);   // (8, 64)

    proj_mma_kernel<<<gproj, 256, PROJ_SMEM>>>(query, Wq, bq, (float*)pQ);
    proj_mma_kernel<<<gproj, 256, PROJ_SMEM>>>(key_,  Wk, bk, (float*)pK);
    proj_mma_kernel<<<gproj, 256, PROJ_SMEM>>>(value, Wv, bv, (float*)pV);

    scores_mma_kernel<<<dim3(S_ / 128, S_ / 128, BH_), 256, SCORES_SMEM>>>(
        (const float*)pQ, (const float*)pK, mask, pout, (float*)pR);

    av_mma_kernel<<<dim3(S_ / 128, BH_), 256, AV_SMEM>>>(
        pout, (const float*)pV, (const float*)pR, (float*)pX);

    proj_mma_kernel<<<gproj, 256, PROJ_SMEM>>>((const float*)pX, Wo, bo, xout);
}